// round 1
// baseline (speedup 1.0000x reference)
#include <cuda_runtime.h>

#define B_ 32
#define S_ 2048
#define F_ 768
#define H_ 8
#define ROWS_ (B_*S_)          // 65536
#define KDIM_ (F_*H_)          // 6144

// Scratch (device globals; no runtime allocation)
__device__ float g_logits[ROWS_*16];   // [row][0..7]=att logits, [8..15]=gate logits
__device__ float g_m[B_*H_];
__device__ float g_invz[B_*H_];
__device__ float g_pooled[B_*KDIM_];   // [b][f][h]

// ---------- packed f32x2 helpers ----------
__device__ __forceinline__ unsigned long long bcast2(float v) {
    unsigned int u = __float_as_uint(v);
    unsigned long long r;
    asm("mov.b64 %0, {%1, %1};" : "=l"(r) : "r"(u));
    return r;
}
__device__ __forceinline__ void ffma2(unsigned long long &d, unsigned long long a, unsigned long long b) {
    asm("fma.rn.f32x2 %0, %1, %2, %0;" : "+l"(d) : "l"(a), "l"(b));
}
__device__ __forceinline__ unsigned long long fadd2(unsigned long long a, unsigned long long b) {
    unsigned long long r;
    asm("add.rn.f32x2 %0, %1, %2;" : "=l"(r) : "l"(a), "l"(b));
    return r;
}
__device__ __forceinline__ float2 unpack2(unsigned long long v) {
    unsigned int lo, hi;
    asm("mov.b64 {%0, %1}, %2;" : "=r"(lo), "=r"(hi) : "l"(v));
    return make_float2(__uint_as_float(lo), __uint_as_float(hi));
}

// ---------- K1: logits = x @ [W_att;W_gate]^T  (att,gate packed as f32x2) ----------
__global__ void __launch_bounds__(256) k_logits(const float* __restrict__ x,
                                                const float* __restrict__ Wa,
                                                const float* __restrict__ Wg) {
    __shared__ __align__(16) float2 Wp[H_*F_];   // Wp[h*768+f] = (Wa[h][f], Wg[h][f]) : 48KB
    for (int i = threadIdx.x; i < H_*F_; i += 256)
        Wp[i] = make_float2(Wa[i], Wg[i]);
    __syncthreads();

    int warp = threadIdx.x >> 5, lane = threadIdx.x & 31;
    int rowbase = (blockIdx.x * 8 + warp) * 4;           // 4 rows per warp
    const float4* xr = reinterpret_cast<const float4*>(x) + (size_t)rowbase * 192;

    unsigned long long v[32];                            // v[r*8+hp] = packed (att_h, gate_h)
    #pragma unroll
    for (int i = 0; i < 32; i++) v[i] = 0ull;

    #pragma unroll
    for (int c = 0; c < 6; c++) {
        float4 xv[4];
        #pragma unroll
        for (int r = 0; r < 4; r++) xv[r] = xr[r*192 + c*32 + lane];
        int e = (c*32 + lane) * 2;                       // ulonglong2 index into a W row
        #pragma unroll
        for (int r = 0; r < 4; r++) {
            unsigned long long xx0 = bcast2(xv[r].x), xx1 = bcast2(xv[r].y);
            unsigned long long xx2 = bcast2(xv[r].z), xx3 = bcast2(xv[r].w);
            #pragma unroll
            for (int hp = 0; hp < 8; hp++) {
                const ulonglong2* wrow = reinterpret_cast<const ulonglong2*>(Wp + hp*F_);
                ulonglong2 wA = wrow[e];                 // pairs for f0,f1
                ulonglong2 wB = wrow[e+1];               // pairs for f2,f3
                ffma2(v[r*8+hp], xx0, wA.x);
                ffma2(v[r*8+hp], xx1, wA.y);
                ffma2(v[r*8+hp], xx2, wB.x);
                ffma2(v[r*8+hp], xx3, wB.y);
            }
        }
    }

    // log-halving reduction: 32 packed values across 32 lanes -> value i lands on lane i
    #pragma unroll
    for (int s = 16; s >= 1; s >>= 1) {
        bool up = (lane & s) != 0;
        #pragma unroll
        for (int i = 0; i < s; i++) {
            unsigned long long send = up ? v[i] : v[i+s];
            unsigned long long recv = __shfl_xor_sync(0xffffffffu, send, s);
            unsigned long long keep = up ? v[i+s] : v[i];
            v[i] = fadd2(keep, recv);
        }
    }

    float2 res = unpack2(v[0]);
    int r = lane >> 3, hp = lane & 7;
    size_t row = (size_t)rowbase + r;
    g_logits[row*16 + hp]     = res.x;   // att logit (b_att omitted: softmax shift-invariant)
    g_logits[row*16 + 8 + hp] = res.y;   // gate logit (b_gate added later)
}

// ---------- K2: per-(b,h) softmax stats + zero pooled ----------
__global__ void __launch_bounds__(256) k_stats() {
    int bh = blockIdx.x;                 // 0..255
    int b = bh >> 3, h = bh & 7;
    for (int i = threadIdx.x; i < F_; i += 256) g_pooled[bh*F_ + i] = 0.f;

    const float* base = g_logits + (size_t)b * S_ * 16 + h;
    float vals[8];
    #pragma unroll
    for (int k = 0; k < 8; k++) vals[k] = base[(threadIdx.x + k*256) * 16];

    float m = vals[0];
    #pragma unroll
    for (int k = 1; k < 8; k++) m = fmaxf(m, vals[k]);
    #pragma unroll
    for (int s = 16; s; s >>= 1) m = fmaxf(m, __shfl_xor_sync(0xffffffffu, m, s));
    __shared__ float smx[8];
    if ((threadIdx.x & 31) == 0) smx[threadIdx.x >> 5] = m;
    __syncthreads();
    float M = smx[0];
    #pragma unroll
    for (int w = 1; w < 8; w++) M = fmaxf(M, smx[w]);

    float z = 0.f;
    #pragma unroll
    for (int k = 0; k < 8; k++) z += __expf(vals[k] - M);
    #pragma unroll
    for (int s = 16; s; s >>= 1) z += __shfl_xor_sync(0xffffffffu, z, s);
    __shared__ float smz[8];
    if ((threadIdx.x & 31) == 0) smz[threadIdx.x >> 5] = z;
    __syncthreads();
    if (threadIdx.x == 0) {
        float Z = 0.f;
        #pragma unroll
        for (int w = 0; w < 8; w++) Z += smz[w];
        g_m[bh] = M;
        g_invz[bh] = 1.f / Z;
    }
}

// ---------- K3: pooled[b,f,h] += w[b,s,h] * x[b,s,f]  (split-S, REDG atomics) ----------
__global__ void __launch_bounds__(192) k_pool(const float* __restrict__ x,
                                              const float* __restrict__ b_gate) {
    int b = blockIdx.y, chunk = blockIdx.x;              // 8 chunks of 256 rows
    __shared__ __align__(16) float wsh[32][8];
    __shared__ float msh[8], izsh[8], bgsh[8];
    if (threadIdx.x < 8) {
        msh[threadIdx.x]  = g_m[b*8 + threadIdx.x];
        izsh[threadIdx.x] = g_invz[b*8 + threadIdx.x];
        bgsh[threadIdx.x] = b_gate[threadIdx.x];
    }

    unsigned long long acc[16];                          // acc[fi*4+hp] packed over (h,h+1)
    #pragma unroll
    for (int i = 0; i < 16; i++) acc[i] = 0ull;

    int srow0 = b*S_ + chunk*256;
    const float4* x4 = reinterpret_cast<const float4*>(x);

    for (int t = 0; t < 8; t++) {                        // 8 tiles of 32 rows
        __syncthreads();
        for (int i = threadIdx.x; i < 256; i += 192) {
            int sl = i >> 3, h = i & 7;
            int row = srow0 + t*32 + sl;
            float a = g_logits[(size_t)row*16 + h];
            float g = g_logits[(size_t)row*16 + 8 + h];
            float w = __expf(a - msh[h]) * izsh[h] * (1.f / (1.f + __expf(-(g + bgsh[h]))));
            wsh[sl][h] = w;
        }
        __syncthreads();
        #pragma unroll
        for (int sl = 0; sl < 32; sl += 4) {
            float4 xv[4];
            #pragma unroll
            for (int j = 0; j < 4; j++)
                xv[j] = x4[(size_t)(srow0 + t*32 + sl + j)*192 + threadIdx.x];
            #pragma unroll
            for (int j = 0; j < 4; j++) {
                unsigned long long xx0 = bcast2(xv[j].x), xx1 = bcast2(xv[j].y);
                unsigned long long xx2 = bcast2(xv[j].z), xx3 = bcast2(xv[j].w);
                #pragma unroll
                for (int hp = 0; hp < 4; hp++) {
                    unsigned long long wp =
                        *reinterpret_cast<const unsigned long long*>(&wsh[sl + j][hp*2]);
                    ffma2(acc[0  + hp], xx0, wp);
                    ffma2(acc[4  + hp], xx1, wp);
                    ffma2(acc[8  + hp], xx2, wp);
                    ffma2(acc[12 + hp], xx3, wp);
                }
            }
        }
    }

    float* pb = g_pooled + b*KDIM_ + threadIdx.x*32;     // thread owns f=4t..4t+3, all 8 h
    #pragma unroll
    for (int fi = 0; fi < 4; fi++)
        #pragma unroll
        for (int hp = 0; hp < 4; hp++) {
            float2 val = unpack2(acc[fi*4 + hp]);
            atomicAdd(pb + fi*8 + hp*2,     val.x);
            atomicAdd(pb + fi*8 + hp*2 + 1, val.y);
        }
}

// ---------- K4: out = pooled_flat @ W_out^T + b_out ----------
__global__ void __launch_bounds__(128) k_out(const float* __restrict__ Wout,
                                             const float* __restrict__ bout,
                                             float* __restrict__ out) {
    __shared__ __align__(16) float ps[32][260];          // padded: conflict-free
    __shared__ __align__(16) float ws[8][260];
    int b2 = threadIdx.x >> 3, j = threadIdx.x & 7;      // tile [32 b x 8 f']
    int fp = blockIdx.x*8 + j;
    unsigned long long acc0 = 0ull, acc1 = 0ull;         // b2 and b2+16, packed over k parity

    for (int kc = 0; kc < KDIM_; kc += 256) {
        __syncthreads();
        for (int i = threadIdx.x; i < 8192; i += 128) {
            int bb = i >> 8, kk = i & 255;
            ps[bb][kk] = g_pooled[bb*KDIM_ + kc + kk];
        }
        for (int i = threadIdx.x; i < 2048; i += 128) {
            int jj = i >> 8, kk = i & 255;
            ws[jj][kk] = Wout[(size_t)(blockIdx.x*8 + jj)*KDIM_ + kc + kk];
        }
        __syncthreads();
        #pragma unroll 8
        for (int k = 0; k < 256; k += 4) {
            ulonglong2 p0 = *reinterpret_cast<const ulonglong2*>(&ps[b2][k]);
            ulonglong2 p1 = *reinterpret_cast<const ulonglong2*>(&ps[b2+16][k]);
            ulonglong2 wv = *reinterpret_cast<const ulonglong2*>(&ws[j][k]);
            ffma2(acc0, p0.x, wv.x);  ffma2(acc0, p0.y, wv.y);
            ffma2(acc1, p1.x, wv.x);  ffma2(acc1, p1.y, wv.y);
        }
    }
    float2 a0 = unpack2(acc0), a1 = unpack2(acc1);
    float bo = bout[fp];
    out[b2*F_ + fp]        = a0.x + a0.y + bo;
    out[(b2+16)*F_ + fp]   = a1.x + a1.y + bo;
}

extern "C" void kernel_launch(void* const* d_in, const int* in_sizes, int n_in,
                              void* d_out, int out_size) {
    const float* x    = (const float*)d_in[0];   // [B,S,F]
    const float* Wa   = (const float*)d_in[1];   // [H,F]
    // d_in[2] = b_att: unused (softmax over s is shift-invariant per (b,h))
    const float* Wg   = (const float*)d_in[3];   // [H,F]
    const float* bg   = (const float*)d_in[4];   // [H]
    const float* Wout = (const float*)d_in[5];   // [F, H*F]
    const float* bout = (const float*)d_in[6];   // [F]
    float* out = (float*)d_out;                  // [B,F]

    k_logits<<<ROWS_/32, 256>>>(x, Wa, Wg);
    k_stats<<<B_*H_, 256>>>();
    k_pool<<<dim3(8, B_), 192>>>(x, bg);
    k_out<<<F_/8, 128>>>(Wout, bout, out);
}

// round 2
// speedup vs baseline: 1.9322x; 1.9322x over previous
#include <cuda_runtime.h>

#define B_ 32
#define S_ 2048
#define F_ 768
#define H_ 8
#define ROWS_ (B_*S_)          // 65536
#define KDIM_ (F_*H_)          // 6144

// Scratch (device globals; no runtime allocation)
__device__ float g_logits[ROWS_*16];   // [row][0..7]=att logits, [8..15]=gate logits
__device__ float g_m[B_*H_];
__device__ float g_invz[B_*H_];
__device__ float g_pooled[B_*KDIM_];   // [b][f][h]

// ---------- packed f32x2 helpers ----------
__device__ __forceinline__ unsigned long long bcast2(float v) {
    unsigned int u = __float_as_uint(v);
    unsigned long long r;
    asm("mov.b64 %0, {%1, %1};" : "=l"(r) : "r"(u));
    return r;
}
__device__ __forceinline__ void ffma2(unsigned long long &d, unsigned long long a, unsigned long long b) {
    asm("fma.rn.f32x2 %0, %1, %2, %0;" : "+l"(d) : "l"(a), "l"(b));
}
__device__ __forceinline__ unsigned long long fadd2(unsigned long long a, unsigned long long b) {
    unsigned long long r;
    asm("add.rn.f32x2 %0, %1, %2;" : "=l"(r) : "l"(a), "l"(b));
    return r;
}
__device__ __forceinline__ float2 unpack2(unsigned long long v) {
    unsigned int lo, hi;
    asm("mov.b64 {%0, %1}, %2;" : "=r"(lo), "=r"(hi) : "l"(v));
    return make_float2(__uint_as_float(lo), __uint_as_float(hi));
}

// ---------- K1: logits = x @ [W_att;W_gate]^T  (att,gate packed as f32x2) ----------
__global__ void __launch_bounds__(256) k_logits(const float* __restrict__ x,
                                                const float* __restrict__ Wa,
                                                const float* __restrict__ Wg) {
    __shared__ __align__(16) float2 Wp[H_*F_];   // Wp[h*768+f] = (Wa[h][f], Wg[h][f]) : 48KB
    for (int i = threadIdx.x; i < H_*F_; i += 256)
        Wp[i] = make_float2(Wa[i], Wg[i]);
    __syncthreads();

    int warp = threadIdx.x >> 5, lane = threadIdx.x & 31;
    int rowbase = (blockIdx.x * 8 + warp) * 4;           // 4 rows per warp
    const float4* xr = reinterpret_cast<const float4*>(x) + (size_t)rowbase * 192;

    unsigned long long v[32];                            // v[r*8+hp] = packed (att_h, gate_h)
    #pragma unroll
    for (int i = 0; i < 32; i++) v[i] = 0ull;

    #pragma unroll
    for (int c = 0; c < 6; c++) {
        float4 xv[4];
        #pragma unroll
        for (int r = 0; r < 4; r++) xv[r] = xr[r*192 + c*32 + lane];
        int e = (c*32 + lane) * 2;                       // ulonglong2 index into a W row
        #pragma unroll
        for (int r = 0; r < 4; r++) {
            unsigned long long xx0 = bcast2(xv[r].x), xx1 = bcast2(xv[r].y);
            unsigned long long xx2 = bcast2(xv[r].z), xx3 = bcast2(xv[r].w);
            #pragma unroll
            for (int hp = 0; hp < 8; hp++) {
                const ulonglong2* wrow = reinterpret_cast<const ulonglong2*>(Wp + hp*F_);
                ulonglong2 wA = wrow[e];
                ulonglong2 wB = wrow[e+1];
                ffma2(v[r*8+hp], xx0, wA.x);
                ffma2(v[r*8+hp], xx1, wA.y);
                ffma2(v[r*8+hp], xx2, wB.x);
                ffma2(v[r*8+hp], xx3, wB.y);
            }
        }
    }

    // log-halving reduction: 32 packed values across 32 lanes -> value i lands on lane i
    #pragma unroll
    for (int s = 16; s >= 1; s >>= 1) {
        bool up = (lane & s) != 0;
        #pragma unroll
        for (int i = 0; i < s; i++) {
            unsigned long long send = up ? v[i] : v[i+s];
            unsigned long long recv = __shfl_xor_sync(0xffffffffu, send, s);
            unsigned long long keep = up ? v[i+s] : v[i];
            v[i] = fadd2(keep, recv);
        }
    }

    float2 res = unpack2(v[0]);
    int r = lane >> 3, hp = lane & 7;
    size_t row = (size_t)rowbase + r;
    g_logits[row*16 + hp]     = res.x;   // att logit (b_att omitted: softmax shift-invariant)
    g_logits[row*16 + 8 + hp] = res.y;   // gate logit (b_gate added later)
}

// ---------- K2: per-(b,h) softmax stats + zero pooled + init out with bias ----------
__global__ void __launch_bounds__(256) k_stats(const float* __restrict__ bout,
                                               float* __restrict__ out) {
    int bh = blockIdx.x;                 // 0..255
    int b = bh >> 3, h = bh & 7;
    for (int i = threadIdx.x; i < F_; i += 256) g_pooled[bh*F_ + i] = 0.f;
    if ((bh & 7) == 0)                   // 32 blocks init one output row each
        for (int i = threadIdx.x; i < F_; i += 256) out[b*F_ + i] = bout[i];

    const float* base = g_logits + (size_t)b * S_ * 16 + h;
    float vals[8];
    #pragma unroll
    for (int k = 0; k < 8; k++) vals[k] = base[(threadIdx.x + k*256) * 16];

    float m = vals[0];
    #pragma unroll
    for (int k = 1; k < 8; k++) m = fmaxf(m, vals[k]);
    #pragma unroll
    for (int s = 16; s; s >>= 1) m = fmaxf(m, __shfl_xor_sync(0xffffffffu, m, s));
    __shared__ float smx[8];
    if ((threadIdx.x & 31) == 0) smx[threadIdx.x >> 5] = m;
    __syncthreads();
    float M = smx[0];
    #pragma unroll
    for (int w = 1; w < 8; w++) M = fmaxf(M, smx[w]);

    float z = 0.f;
    #pragma unroll
    for (int k = 0; k < 8; k++) z += __expf(vals[k] - M);
    #pragma unroll
    for (int s = 16; s; s >>= 1) z += __shfl_xor_sync(0xffffffffu, z, s);
    __shared__ float smz[8];
    if ((threadIdx.x & 31) == 0) smz[threadIdx.x >> 5] = z;
    __syncthreads();
    if (threadIdx.x == 0) {
        float Z = 0.f;
        #pragma unroll
        for (int w = 0; w < 8; w++) Z += smz[w];
        g_m[bh] = M;
        g_invz[bh] = 1.f / Z;
    }
}

// ---------- K3: pooled[b,f,h] += w[b,s,h] * x[b,s,f]  (split-S, REDG atomics) ----------
__global__ void __launch_bounds__(192) k_pool(const float* __restrict__ x,
                                              const float* __restrict__ b_gate) {
    int b = blockIdx.y, chunk = blockIdx.x;              // 8 chunks of 256 rows
    __shared__ __align__(16) float wsh[32][8];
    __shared__ float msh[8], izsh[8], bgsh[8];
    if (threadIdx.x < 8) {
        msh[threadIdx.x]  = g_m[b*8 + threadIdx.x];
        izsh[threadIdx.x] = g_invz[b*8 + threadIdx.x];
        bgsh[threadIdx.x] = b_gate[threadIdx.x];
    }

    unsigned long long acc[16];                          // acc[fi*4+hp] packed over (h,h+1)
    #pragma unroll
    for (int i = 0; i < 16; i++) acc[i] = 0ull;

    int srow0 = b*S_ + chunk*256;
    const float4* x4 = reinterpret_cast<const float4*>(x);

    for (int t = 0; t < 8; t++) {                        // 8 tiles of 32 rows
        __syncthreads();
        for (int i = threadIdx.x; i < 256; i += 192) {
            int sl = i >> 3, h = i & 7;
            int row = srow0 + t*32 + sl;
            float a = g_logits[(size_t)row*16 + h];
            float g = g_logits[(size_t)row*16 + 8 + h];
            float w = __expf(a - msh[h]) * izsh[h] * (1.f / (1.f + __expf(-(g + bgsh[h]))));
            wsh[sl][h] = w;
        }
        __syncthreads();
        #pragma unroll
        for (int sl = 0; sl < 32; sl += 4) {
            float4 xv[4];
            #pragma unroll
            for (int j = 0; j < 4; j++)
                xv[j] = x4[(size_t)(srow0 + t*32 + sl + j)*192 + threadIdx.x];
            #pragma unroll
            for (int j = 0; j < 4; j++) {
                unsigned long long xx0 = bcast2(xv[j].x), xx1 = bcast2(xv[j].y);
                unsigned long long xx2 = bcast2(xv[j].z), xx3 = bcast2(xv[j].w);
                #pragma unroll
                for (int hp = 0; hp < 4; hp++) {
                    unsigned long long wp =
                        *reinterpret_cast<const unsigned long long*>(&wsh[sl + j][hp*2]);
                    ffma2(acc[0  + hp], xx0, wp);
                    ffma2(acc[4  + hp], xx1, wp);
                    ffma2(acc[8  + hp], xx2, wp);
                    ffma2(acc[12 + hp], xx3, wp);
                }
            }
        }
    }

    float* pb = g_pooled + b*KDIM_ + threadIdx.x*32;     // thread owns f=4t..4t+3, all 8 h
    #pragma unroll
    for (int fi = 0; fi < 4; fi++)
        #pragma unroll
        for (int hp = 0; hp < 4; hp++) {
            float2 val = unpack2(acc[fi*4 + hp]);
            atomicAdd(pb + fi*8 + hp*2,     val.x);
            atomicAdd(pb + fi*8 + hp*2 + 1, val.y);
        }
}

// ---------- K4 v2: out += pooled_flat @ W_out^T  (split-K, 144 blocks, reg-blocked) ----------
#define NT_ 128      // output-column tile per block
#define KT_ 256      // K range per block (grid.y = 6144/256 = 24)
#define KSUB_ 64     // K staged in smem per iteration

__global__ void __launch_bounds__(256) k_out2(const float* __restrict__ Wout,
                                              float* __restrict__ out) {
    __shared__ __align__(16) float ws[NT_][KSUB_ + 2];   // stride 66: <=2-way LDS conflicts
    __shared__ __align__(16) float ps[32][KSUB_ + 2];
    int n0 = blockIdx.x * NT_;
    int k0 = blockIdx.y * KT_;
    int cidx = threadIdx.x & 31;         // col within group; cols = cidx + cc*32
    int bq   = threadIdx.x >> 5;         // warp id -> rows bq*4 .. bq*4+3

    unsigned long long acc[4][4];        // [row r][col group cc], packed over k-pairs
    #pragma unroll
    for (int r = 0; r < 4; r++)
        #pragma unroll
        for (int c = 0; c < 4; c++) acc[r][c] = 0ull;

    for (int sub = 0; sub < KT_/KSUB_; sub++) {
        int kb = k0 + sub*KSUB_;
        __syncthreads();
        // stage Wout tile: 128 cols x 64 k (float2 loads, coalesced per row)
        #pragma unroll 4
        for (int i = threadIdx.x; i < NT_*32; i += 256) {
            int c = i >> 5, kq = i & 31;
            *reinterpret_cast<float2*>(&ws[c][kq*2]) =
                *reinterpret_cast<const float2*>(&Wout[(size_t)(n0 + c)*KDIM_ + kb + kq*2]);
        }
        // stage pooled tile: 32 rows x 64 k
        #pragma unroll 4
        for (int i = threadIdx.x; i < 32*32; i += 256) {
            int rr = i >> 5, kq = i & 31;
            *reinterpret_cast<float2*>(&ps[rr][kq*2]) =
                *reinterpret_cast<const float2*>(&g_pooled[(size_t)rr*KDIM_ + kb + kq*2]);
        }
        __syncthreads();

        #pragma unroll 4
        for (int kk = 0; kk < KSUB_/2; kk++) {
            unsigned long long pv[4], wv[4];
            #pragma unroll
            for (int r = 0; r < 4; r++)
                pv[r] = *reinterpret_cast<const unsigned long long*>(&ps[bq*4 + r][kk*2]);
            #pragma unroll
            for (int c = 0; c < 4; c++)
                wv[c] = *reinterpret_cast<const unsigned long long*>(&ws[cidx + c*32][kk*2]);
            #pragma unroll
            for (int r = 0; r < 4; r++)
                #pragma unroll
                for (int c = 0; c < 4; c++)
                    ffma2(acc[r][c], pv[r], wv[c]);
        }
    }

    #pragma unroll
    for (int r = 0; r < 4; r++)
        #pragma unroll
        for (int c = 0; c < 4; c++) {
            float2 v = unpack2(acc[r][c]);
            atomicAdd(&out[(size_t)(bq*4 + r)*F_ + n0 + cidx + c*32], v.x + v.y);
        }
}

extern "C" void kernel_launch(void* const* d_in, const int* in_sizes, int n_in,
                              void* d_out, int out_size) {
    const float* x    = (const float*)d_in[0];   // [B,S,F]
    const float* Wa   = (const float*)d_in[1];   // [H,F]
    // d_in[2] = b_att: unused (softmax over s is shift-invariant per (b,h))
    const float* Wg   = (const float*)d_in[3];   // [H,F]
    const float* bg   = (const float*)d_in[4];   // [H]
    const float* Wout = (const float*)d_in[5];   // [F, H*F]
    const float* bout = (const float*)d_in[6];   // [F]
    float* out = (float*)d_out;                  // [B,F]

    k_logits<<<ROWS_/32, 256>>>(x, Wa, Wg);
    k_stats<<<B_*H_, 256>>>(bout, out);
    k_pool<<<dim3(8, B_), 192>>>(x, bg);
    k_out2<<<dim3(F_/NT_, KDIM_/KT_), 256>>>(Wout, out);
}

// round 3
// speedup vs baseline: 1.9377x; 1.0028x over previous
#include <cuda_runtime.h>

#define B_ 32
#define S_ 2048
#define F_ 768
#define H_ 8
#define ROWS_ (B_*S_)          // 65536
#define KDIM_ (F_*H_)          // 6144

// Scratch (device globals; no runtime allocation)
__device__ float g_logits[ROWS_*16];   // [row][0..7]=att logits, [8..15]=gate logits
__device__ float g_m[B_*H_];
__device__ float g_invz[B_*H_];
__device__ float g_pooled[B_*KDIM_];   // [b][f][h]

// ---------- packed f32x2 helpers ----------
__device__ __forceinline__ unsigned long long bcast2(float v) {
    unsigned int u = __float_as_uint(v);
    unsigned long long r;
    asm("mov.b64 %0, {%1, %1};" : "=l"(r) : "r"(u));
    return r;
}
__device__ __forceinline__ unsigned long long pack2(float a, float b) {
    unsigned long long r;
    asm("mov.b64 %0, {%1, %2};" : "=l"(r)
        : "r"(__float_as_uint(a)), "r"(__float_as_uint(b)));
    return r;
}
__device__ __forceinline__ void ffma2(unsigned long long &d, unsigned long long a, unsigned long long b) {
    asm("fma.rn.f32x2 %0, %1, %2, %0;" : "+l"(d) : "l"(a), "l"(b));
}
__device__ __forceinline__ unsigned long long fadd2(unsigned long long a, unsigned long long b) {
    unsigned long long r;
    asm("add.rn.f32x2 %0, %1, %2;" : "=l"(r) : "l"(a), "l"(b));
    return r;
}
__device__ __forceinline__ float2 unpack2(unsigned long long v) {
    unsigned int lo, hi;
    asm("mov.b64 {%0, %1}, %2;" : "=r"(lo), "=r"(hi) : "l"(v));
    return make_float2(__uint_as_float(lo), __uint_as_float(hi));
}

// ---------- K1 v2: logits, conflict-free LDS (lane owns an f-pair, 16B stride) ----------
__global__ void __launch_bounds__(256) k_logits(const float* __restrict__ x,
                                                const float* __restrict__ Wa,
                                                const float* __restrict__ Wg) {
    __shared__ __align__(16) unsigned long long Wp[H_*F_];   // Wp[h*768+f]=(att,gate) : 48KB
    for (int i = threadIdx.x; i < H_*F_; i += 256)
        Wp[i] = pack2(Wa[i], Wg[i]);
    __syncthreads();

    int warp = threadIdx.x >> 5, lane = threadIdx.x & 31;
    int rowbase = (blockIdx.x * 8 + warp) * 4;               // 4 rows per warp
    const float2* xr = reinterpret_cast<const float2*>(x) + (size_t)rowbase * 384;

    unsigned long long v[32];                                // v[r*8+h] = packed (att_h, gate_h)
    #pragma unroll
    for (int i = 0; i < 32; i++) v[i] = 0ull;

    #pragma unroll
    for (int c = 0; c < 12; c++) {                           // 64 f per iter; lane covers f=c*64+2l..+1
        float2 xv[4];
        #pragma unroll
        for (int r = 0; r < 4; r++) xv[r] = xr[r*384 + c*32 + lane];
        unsigned long long xb[8];
        #pragma unroll
        for (int r = 0; r < 4; r++) { xb[2*r] = bcast2(xv[r].x); xb[2*r+1] = bcast2(xv[r].y); }
        int u = c*32 + lane;                                 // ulonglong2 index into a W row
        #pragma unroll
        for (int h = 0; h < 8; h++) {
            ulonglong2 w = reinterpret_cast<const ulonglong2*>(Wp + h*F_)[u]; // 16B lane stride
            #pragma unroll
            for (int r = 0; r < 4; r++) {
                ffma2(v[r*8+h], xb[2*r],   w.x);
                ffma2(v[r*8+h], xb[2*r+1], w.y);
            }
        }
    }

    // log-halving reduction: 32 packed values across 32 lanes -> value i lands on lane i
    #pragma unroll
    for (int s = 16; s >= 1; s >>= 1) {
        bool up = (lane & s) != 0;
        #pragma unroll
        for (int i = 0; i < s; i++) {
            unsigned long long send = up ? v[i] : v[i+s];
            unsigned long long recv = __shfl_xor_sync(0xffffffffu, send, s);
            unsigned long long keep = up ? v[i+s] : v[i];
            v[i] = fadd2(keep, recv);
        }
    }

    float2 res = unpack2(v[0]);
    int r = lane >> 3, h = lane & 7;
    size_t row = (size_t)rowbase + r;
    g_logits[row*16 + h]     = res.x;   // att logit (b_att omitted: softmax shift-invariant)
    g_logits[row*16 + 8 + h] = res.y;   // gate logit (b_gate added later)
}

// ---------- K2: per-(b,h) softmax stats + zero pooled + init out with bias ----------
__global__ void __launch_bounds__(256) k_stats(const float* __restrict__ bout,
                                               float* __restrict__ out) {
    int bh = blockIdx.x;                 // 0..255
    int b = bh >> 3, h = bh & 7;
    for (int i = threadIdx.x; i < F_; i += 256) g_pooled[bh*F_ + i] = 0.f;
    if ((bh & 7) == 0)
        for (int i = threadIdx.x; i < F_; i += 256) out[b*F_ + i] = bout[i];

    const float* base = g_logits + (size_t)b * S_ * 16 + h;
    float vals[8];
    #pragma unroll
    for (int k = 0; k < 8; k++) vals[k] = base[(threadIdx.x + k*256) * 16];

    float m = vals[0];
    #pragma unroll
    for (int k = 1; k < 8; k++) m = fmaxf(m, vals[k]);
    #pragma unroll
    for (int s = 16; s; s >>= 1) m = fmaxf(m, __shfl_xor_sync(0xffffffffu, m, s));
    __shared__ float smx[8];
    if ((threadIdx.x & 31) == 0) smx[threadIdx.x >> 5] = m;
    __syncthreads();
    float M = smx[0];
    #pragma unroll
    for (int w = 1; w < 8; w++) M = fmaxf(M, smx[w]);

    float z = 0.f;
    #pragma unroll
    for (int k = 0; k < 8; k++) z += __expf(vals[k] - M);
    #pragma unroll
    for (int s = 16; s; s >>= 1) z += __shfl_xor_sync(0xffffffffu, z, s);
    __shared__ float smz[8];
    if ((threadIdx.x & 31) == 0) smz[threadIdx.x >> 5] = z;
    __syncthreads();
    if (threadIdx.x == 0) {
        float Z = 0.f;
        #pragma unroll
        for (int w = 0; w < 8; w++) Z += smz[w];
        g_m[bh] = M;
        g_invz[bh] = 1.f / Z;
    }
}

// ---------- K3 v2: pooled += w * x  (1024 blocks of 64 rows, 8-deep LDG batching) ----------
__global__ void __launch_bounds__(192) k_pool(const float* __restrict__ x,
                                              const float* __restrict__ b_gate) {
    int b = blockIdx.y, chunk = blockIdx.x;              // 32 chunks of 64 rows
    __shared__ __align__(16) float wsh[64][8];
    __shared__ float msh[8], izsh[8], bgsh[8];
    if (threadIdx.x < 8) {
        msh[threadIdx.x]  = g_m[b*8 + threadIdx.x];
        izsh[threadIdx.x] = g_invz[b*8 + threadIdx.x];
        bgsh[threadIdx.x] = b_gate[threadIdx.x];
    }
    __syncthreads();

    int srow0 = b*S_ + chunk*64;
    for (int i = threadIdx.x; i < 512; i += 192) {
        int sl = i >> 3, h = i & 7;
        int row = srow0 + sl;
        float a = g_logits[(size_t)row*16 + h];
        float g = g_logits[(size_t)row*16 + 8 + h];
        wsh[sl][h] = __expf(a - msh[h]) * izsh[h] * (1.f / (1.f + __expf(-(g + bgsh[h]))));
    }
    __syncthreads();

    unsigned long long acc[16];                          // acc[fi*4+hp] packed over (h,h+1)
    #pragma unroll
    for (int i = 0; i < 16; i++) acc[i] = 0ull;

    const float4* x4 = reinterpret_cast<const float4*>(x);
    #pragma unroll 1
    for (int sl = 0; sl < 64; sl += 8) {
        float4 xv[8];
        #pragma unroll
        for (int j = 0; j < 8; j++)
            xv[j] = x4[(size_t)(srow0 + sl + j)*192 + threadIdx.x];
        #pragma unroll
        for (int j = 0; j < 8; j++) {
            unsigned long long xx0 = bcast2(xv[j].x), xx1 = bcast2(xv[j].y);
            unsigned long long xx2 = bcast2(xv[j].z), xx3 = bcast2(xv[j].w);
            #pragma unroll
            for (int hp = 0; hp < 4; hp++) {
                unsigned long long wp =
                    *reinterpret_cast<const unsigned long long*>(&wsh[sl + j][hp*2]);
                ffma2(acc[0  + hp], xx0, wp);
                ffma2(acc[4  + hp], xx1, wp);
                ffma2(acc[8  + hp], xx2, wp);
                ffma2(acc[12 + hp], xx3, wp);
            }
        }
    }

    float* pb = g_pooled + b*KDIM_ + threadIdx.x*32;     // thread owns f=4t..4t+3, all 8 h
    #pragma unroll
    for (int fi = 0; fi < 4; fi++)
        #pragma unroll
        for (int hp = 0; hp < 4; hp++) {
            float2 val = unpack2(acc[fi*4 + hp]);
            atomicAdd(pb + fi*8 + hp*2,     val.x);
            atomicAdd(pb + fi*8 + hp*2 + 1, val.y);
        }
}

// ---------- K4 v3: out += pooled @ Wout^T  (288 blocks, double-buffered, swizzled) ----------
#define NT_ 64       // output-column tile per block (grid.x = 12)
#define KT_ 256      // K range per block (grid.y = 24)
#define KSUB_ 64     // K staged per buffer (32 ull units of 8B)

__global__ void __launch_bounds__(256) k_out3(const float* __restrict__ Wout,
                                              float* __restrict__ out) {
    __shared__ unsigned long long ws[2][NT_][32];        // rotation-swizzled: phys=(k+col)&31
    __shared__ unsigned long long ps[2][32][32];         // 48KB total
    int n0 = blockIdx.x * NT_;
    int k0h = blockIdx.y * (KT_/2);                      // in float2 units
    int cidx = threadIdx.x & 31;
    int bq   = threadIdx.x >> 5;                         // warp -> rows bq*4..bq*4+3
    const float2* W2 = reinterpret_cast<const float2*>(Wout);
    const float2* P2 = reinterpret_cast<const float2*>(g_pooled);

    int wc = threadIdx.x >> 5;                           // staging: base col/row
    int kq = threadIdx.x & 31;

    float2 rw[8], rp[4];
    // prefetch sub 0
    #pragma unroll
    for (int s = 0; s < 8; s++)
        rw[s] = W2[(size_t)(n0 + wc + s*8)*(KDIM_/2) + k0h + kq];
    #pragma unroll
    for (int s = 0; s < 4; s++)
        rp[s] = P2[(size_t)(wc + s*8)*(KDIM_/2) + k0h + kq];
    #pragma unroll
    for (int s = 0; s < 8; s++)
        ws[0][wc + s*8][(kq + wc + s*8) & 31] = pack2(rw[s].x, rw[s].y);
    #pragma unroll
    for (int s = 0; s < 4; s++)
        ps[0][wc + s*8][kq] = pack2(rp[s].x, rp[s].y);
    __syncthreads();

    unsigned long long acc[4][2];
    #pragma unroll
    for (int r = 0; r < 4; r++) { acc[r][0] = 0ull; acc[r][1] = 0ull; }

    #pragma unroll 1
    for (int sub = 0; sub < KT_/KSUB_; sub++) {
        if (sub < KT_/KSUB_ - 1) {
            int kh = k0h + (sub+1)*32;
            #pragma unroll
            for (int s = 0; s < 8; s++)
                rw[s] = W2[(size_t)(n0 + wc + s*8)*(KDIM_/2) + kh + kq];
            #pragma unroll
            for (int s = 0; s < 4; s++)
                rp[s] = P2[(size_t)(wc + s*8)*(KDIM_/2) + kh + kq];
        }
        int buf = sub & 1;
        #pragma unroll 8
        for (int kk = 0; kk < 32; kk++) {
            int ph = (kk + cidx) & 31;
            unsigned long long wv0 = ws[buf][cidx][ph];
            unsigned long long wv1 = ws[buf][cidx + 32][ph];
            #pragma unroll
            for (int r = 0; r < 4; r++) {
                unsigned long long pv = ps[buf][bq*4 + r][kk];
                ffma2(acc[r][0], pv, wv0);
                ffma2(acc[r][1], pv, wv1);
            }
        }
        if (sub < KT_/KSUB_ - 1) {
            int nb = (sub + 1) & 1;
            #pragma unroll
            for (int s = 0; s < 8; s++)
                ws[nb][wc + s*8][(kq + wc + s*8) & 31] = pack2(rw[s].x, rw[s].y);
            #pragma unroll
            for (int s = 0; s < 4; s++)
                ps[nb][wc + s*8][kq] = pack2(rp[s].x, rp[s].y);
            __syncthreads();
        }
    }

    #pragma unroll
    for (int r = 0; r < 4; r++)
        #pragma unroll
        for (int c = 0; c < 2; c++) {
            float2 v = unpack2(acc[r][c]);
            atomicAdd(&out[(size_t)(bq*4 + r)*F_ + n0 + cidx + c*32], v.x + v.y);
        }
}

extern "C" void kernel_launch(void* const* d_in, const int* in_sizes, int n_in,
                              void* d_out, int out_size) {
    const float* x    = (const float*)d_in[0];   // [B,S,F]
    const float* Wa   = (const float*)d_in[1];   // [H,F]
    // d_in[2] = b_att: unused (softmax over s is shift-invariant per (b,h))
    const float* Wg   = (const float*)d_in[3];   // [H,F]
    const float* bg   = (const float*)d_in[4];   // [H]
    const float* Wout = (const float*)d_in[5];   // [F, H*F]
    const float* bout = (const float*)d_in[6];   // [F]
    float* out = (float*)d_out;                  // [B,F]

    k_logits<<<ROWS_/32, 256>>>(x, Wa, Wg);
    k_stats<<<B_*H_, 256>>>(bout, out);
    k_pool<<<dim3(32, B_), 192>>>(x, bg);
    k_out3<<<dim3(F_/NT_, KDIM_/KT_), 256>>>(Wout, out);
}

// round 4
// speedup vs baseline: 1.9384x; 1.0004x over previous
#include <cuda_runtime.h>

#define B_ 32
#define S_ 2048
#define F_ 768
#define H_ 8
#define ROWS_ (B_*S_)          // 65536
#define KDIM_ (F_*H_)          // 6144

// Scratch (device globals; no runtime allocation)
__device__ float g_logits[ROWS_*16];   // [row][0..7]=att logits, [8..15]=gate logits
__device__ float g_attT[B_*H_*S_];     // transposed att logits for k_stats
__device__ float g_m[B_*H_];
__device__ float g_invz[B_*H_];
__device__ float g_pooled[B_*KDIM_];   // [b][f][h]

// ---------- packed f32x2 helpers ----------
__device__ __forceinline__ unsigned long long bcast2(float v) {
    unsigned int u = __float_as_uint(v);
    unsigned long long r;
    asm("mov.b64 %0, {%1, %1};" : "=l"(r) : "r"(u));
    return r;
}
__device__ __forceinline__ unsigned long long pack2(float a, float b) {
    unsigned long long r;
    asm("mov.b64 %0, {%1, %2};" : "=l"(r)
        : "r"(__float_as_uint(a)), "r"(__float_as_uint(b)));
    return r;
}
__device__ __forceinline__ void ffma2(unsigned long long &d, unsigned long long a, unsigned long long b) {
    asm("fma.rn.f32x2 %0, %1, %2, %0;" : "+l"(d) : "l"(a), "l"(b));
}
__device__ __forceinline__ unsigned long long fadd2(unsigned long long a, unsigned long long b) {
    unsigned long long r;
    asm("add.rn.f32x2 %0, %1, %2;" : "=l"(r) : "l"(a), "l"(b));
    return r;
}
__device__ __forceinline__ float2 unpack2(unsigned long long v) {
    unsigned int lo, hi;
    asm("mov.b64 {%0, %1}, %2;" : "=r"(lo), "=r"(hi) : "l"(v));
    return make_float2(__uint_as_float(lo), __uint_as_float(hi));
}

// ---------- K0: zero pooled, init out with bias (also shifts ncu capture slot) ----------
__global__ void __launch_bounds__(256) k_init(const float* __restrict__ bout,
                                              float* __restrict__ out) {
    int b = blockIdx.x;
    for (int i = threadIdx.x; i < KDIM_; i += 256) g_pooled[b*KDIM_ + i] = 0.f;
    for (int i = threadIdx.x; i < F_; i += 256) out[b*F_ + i] = bout[i];
}

// ---------- K1 v3: logits with x register double-buffering ----------
__global__ void __launch_bounds__(256) k_logits(const float* __restrict__ x,
                                                const float* __restrict__ Wa,
                                                const float* __restrict__ Wg) {
    __shared__ __align__(16) unsigned long long Wp[H_*F_];   // (att,gate) per f : 48KB
    for (int i = threadIdx.x; i < H_*F_; i += 256)
        Wp[i] = pack2(Wa[i], Wg[i]);
    __syncthreads();

    int warp = threadIdx.x >> 5, lane = threadIdx.x & 31;
    int rowbase = (blockIdx.x * 8 + warp) * 4;               // 4 rows per warp
    const float2* xr = reinterpret_cast<const float2*>(x) + (size_t)rowbase * 384;

    unsigned long long v[32];                                // v[r*8+h] = (att_h, gate_h)
    #pragma unroll
    for (int i = 0; i < 32; i++) v[i] = 0ull;

    float2 cur[4], nxt[4];
    #pragma unroll
    for (int r = 0; r < 4; r++) cur[r] = xr[r*384 + lane];

    #pragma unroll
    for (int c = 0; c < 12; c++) {
        if (c < 11) {
            #pragma unroll
            for (int r = 0; r < 4; r++) nxt[r] = xr[r*384 + (c+1)*32 + lane];
        }
        unsigned long long xb[8];
        #pragma unroll
        for (int r = 0; r < 4; r++) { xb[2*r] = bcast2(cur[r].x); xb[2*r+1] = bcast2(cur[r].y); }
        int u = c*32 + lane;
        #pragma unroll
        for (int h = 0; h < 8; h++) {
            ulonglong2 w = reinterpret_cast<const ulonglong2*>(Wp + h*F_)[u]; // conflict-free
            #pragma unroll
            for (int r = 0; r < 4; r++) {
                ffma2(v[r*8+h], xb[2*r],   w.x);
                ffma2(v[r*8+h], xb[2*r+1], w.y);
            }
        }
        if (c < 11) {
            #pragma unroll
            for (int r = 0; r < 4; r++) cur[r] = nxt[r];
        }
    }

    // log-halving reduction: value i lands on lane i
    #pragma unroll
    for (int s = 16; s >= 1; s >>= 1) {
        bool up = (lane & s) != 0;
        #pragma unroll
        for (int i = 0; i < s; i++) {
            unsigned long long send = up ? v[i] : v[i+s];
            unsigned long long recv = __shfl_xor_sync(0xffffffffu, send, s);
            unsigned long long keep = up ? v[i+s] : v[i];
            v[i] = fadd2(keep, recv);
        }
    }

    float2 res = unpack2(v[0]);
    int r = lane >> 3, h = lane & 7;
    int row = rowbase + r;
    g_logits[(size_t)row*16 + h]     = res.x;   // att (b_att omitted: shift-invariant)
    g_logits[(size_t)row*16 + 8 + h] = res.y;   // gate (b_gate added later)
    g_attT[(size_t)((row >> 11)*8 + h)*S_ + (row & 2047)] = res.x;
}

// ---------- K2 v3: per-(b,h) softmax stats from contiguous g_attT ----------
__global__ void __launch_bounds__(256) k_stats() {
    int bh = blockIdx.x;                 // 0..255
    const float* base = g_attT + (size_t)bh * S_;
    float vals[8];
    #pragma unroll
    for (int k = 0; k < 8; k++) vals[k] = base[threadIdx.x + k*256];

    float m = vals[0];
    #pragma unroll
    for (int k = 1; k < 8; k++) m = fmaxf(m, vals[k]);
    #pragma unroll
    for (int s = 16; s; s >>= 1) m = fmaxf(m, __shfl_xor_sync(0xffffffffu, m, s));
    __shared__ float smx[8];
    if ((threadIdx.x & 31) == 0) smx[threadIdx.x >> 5] = m;
    __syncthreads();
    float M = smx[0];
    #pragma unroll
    for (int w = 1; w < 8; w++) M = fmaxf(M, smx[w]);

    float z = 0.f;
    #pragma unroll
    for (int k = 0; k < 8; k++) z += __expf(vals[k] - M);
    #pragma unroll
    for (int s = 16; s; s >>= 1) z += __shfl_xor_sync(0xffffffffu, z, s);
    __shared__ float smz[8];
    if ((threadIdx.x & 31) == 0) smz[threadIdx.x >> 5] = z;
    __syncthreads();
    if (threadIdx.x == 0) {
        float Z = 0.f;
        #pragma unroll
        for (int w = 0; w < 8; w++) Z += smz[w];
        g_m[bh] = M;
        g_invz[bh] = 1.f / Z;
    }
}

// ---------- K3 v3: pooled += w * x  (prefetched 8-row batches) ----------
__global__ void __launch_bounds__(192) k_pool(const float* __restrict__ x,
                                              const float* __restrict__ b_gate) {
    int b = blockIdx.y, chunk = blockIdx.x;              // 32 chunks of 64 rows
    __shared__ __align__(16) float wsh[64][8];
    __shared__ float msh[8], izsh[8], bgsh[8];
    if (threadIdx.x < 8) {
        msh[threadIdx.x]  = g_m[b*8 + threadIdx.x];
        izsh[threadIdx.x] = g_invz[b*8 + threadIdx.x];
        bgsh[threadIdx.x] = b_gate[threadIdx.x];
    }
    __syncthreads();

    int srow0 = b*S_ + chunk*64;
    for (int i = threadIdx.x; i < 512; i += 192) {
        int sl = i >> 3, h = i & 7;
        int row = srow0 + sl;
        float a = g_logits[(size_t)row*16 + h];
        float g = g_logits[(size_t)row*16 + 8 + h];
        wsh[sl][h] = __expf(a - msh[h]) * izsh[h] * (1.f / (1.f + __expf(-(g + bgsh[h]))));
    }
    __syncthreads();

    unsigned long long acc[16];                          // acc[fi*4+hp]
    #pragma unroll
    for (int i = 0; i < 16; i++) acc[i] = 0ull;

    const float4* x4 = reinterpret_cast<const float4*>(x);
    float4 cur[8], nxt[8];
    #pragma unroll
    for (int j = 0; j < 8; j++)
        cur[j] = x4[(size_t)(srow0 + j)*192 + threadIdx.x];

    #pragma unroll
    for (int sl = 0; sl < 64; sl += 8) {
        if (sl < 56) {
            #pragma unroll
            for (int j = 0; j < 8; j++)
                nxt[j] = x4[(size_t)(srow0 + sl + 8 + j)*192 + threadIdx.x];
        }
        #pragma unroll
        for (int j = 0; j < 8; j++) {
            unsigned long long xx0 = bcast2(cur[j].x), xx1 = bcast2(cur[j].y);
            unsigned long long xx2 = bcast2(cur[j].z), xx3 = bcast2(cur[j].w);
            #pragma unroll
            for (int hp = 0; hp < 4; hp++) {
                unsigned long long wp =
                    *reinterpret_cast<const unsigned long long*>(&wsh[sl + j][hp*2]);
                ffma2(acc[0  + hp], xx0, wp);
                ffma2(acc[4  + hp], xx1, wp);
                ffma2(acc[8  + hp], xx2, wp);
                ffma2(acc[12 + hp], xx3, wp);
            }
        }
        if (sl < 56) {
            #pragma unroll
            for (int j = 0; j < 8; j++) cur[j] = nxt[j];
        }
    }

    float* pb = g_pooled + b*KDIM_ + threadIdx.x*32;     // thread owns 4 f, all 8 h
    #pragma unroll
    for (int fi = 0; fi < 4; fi++)
        #pragma unroll
        for (int hp = 0; hp < 4; hp++) {
            float2 val = unpack2(acc[fi*4 + hp]);
            atomicAdd(pb + fi*8 + hp*2,     val.x);
            atomicAdd(pb + fi*8 + hp*2 + 1, val.y);
        }
}

// ---------- K4 v4: out += pooled @ Wout^T  (576 blocks, double-buffered, swizzled) ----------
#define NT_ 64       // output-column tile per block (grid.x = 12)
#define KT_ 128      // K range per block (grid.y = 48)
#define KSUB_ 64     // K staged per buffer (32 ull units)

__global__ void __launch_bounds__(256) k_out4(const float* __restrict__ Wout,
                                              float* __restrict__ out) {
    __shared__ unsigned long long ws[2][NT_][32];        // rotation-swizzled: phys=(k+col)&31
    __shared__ unsigned long long ps[2][32][32];
    int n0 = blockIdx.x * NT_;
    int k0h = blockIdx.y * (KT_/2);                      // in float2 units
    int cidx = threadIdx.x & 31;
    int bq   = threadIdx.x >> 5;                         // warp -> rows bq*4..bq*4+3
    const float2* W2 = reinterpret_cast<const float2*>(Wout);
    const float2* P2 = reinterpret_cast<const float2*>(g_pooled);

    int wc = threadIdx.x >> 5;
    int kq = threadIdx.x & 31;

    float2 rw[8], rp[4];
    #pragma unroll
    for (int s = 0; s < 8; s++)
        rw[s] = W2[(size_t)(n0 + wc + s*8)*(KDIM_/2) + k0h + kq];
    #pragma unroll
    for (int s = 0; s < 4; s++)
        rp[s] = P2[(size_t)(wc + s*8)*(KDIM_/2) + k0h + kq];
    #pragma unroll
    for (int s = 0; s < 8; s++)
        ws[0][wc + s*8][(kq + wc + s*8) & 31] = pack2(rw[s].x, rw[s].y);
    #pragma unroll
    for (int s = 0; s < 4; s++)
        ps[0][wc + s*8][kq] = pack2(rp[s].x, rp[s].y);
    __syncthreads();

    unsigned long long acc[4][2];
    #pragma unroll
    for (int r = 0; r < 4; r++) { acc[r][0] = 0ull; acc[r][1] = 0ull; }

    #pragma unroll
    for (int sub = 0; sub < KT_/KSUB_; sub++) {
        if (sub < KT_/KSUB_ - 1) {
            int kh = k0h + (sub+1)*32;
            #pragma unroll
            for (int s = 0; s < 8; s++)
                rw[s] = W2[(size_t)(n0 + wc + s*8)*(KDIM_/2) + kh + kq];
            #pragma unroll
            for (int s = 0; s < 4; s++)
                rp[s] = P2[(size_t)(wc + s*8)*(KDIM_/2) + kh + kq];
        }
        int buf = sub & 1;
        #pragma unroll 8
        for (int kk = 0; kk < 32; kk++) {
            int ph = (kk + cidx) & 31;
            unsigned long long wv0 = ws[buf][cidx][ph];
            unsigned long long wv1 = ws[buf][cidx + 32][ph];
            #pragma unroll
            for (int r = 0; r < 4; r++) {
                unsigned long long pv = ps[buf][bq*4 + r][kk];
                ffma2(acc[r][0], pv, wv0);
                ffma2(acc[r][1], pv, wv1);
            }
        }
        if (sub < KT_/KSUB_ - 1) {
            int nb = (sub + 1) & 1;
            #pragma unroll
            for (int s = 0; s < 8; s++)
                ws[nb][wc + s*8][(kq + wc + s*8) & 31] = pack2(rw[s].x, rw[s].y);
            #pragma unroll
            for (int s = 0; s < 4; s++)
                ps[nb][wc + s*8][kq] = pack2(rp[s].x, rp[s].y);
            __syncthreads();
        }
    }

    #pragma unroll
    for (int r = 0; r < 4; r++)
        #pragma unroll
        for (int c = 0; c < 2; c++) {
            float2 v = unpack2(acc[r][c]);
            atomicAdd(&out[(size_t)(bq*4 + r)*F_ + n0 + cidx + c*32], v.x + v.y);
        }
}

extern "C" void kernel_launch(void* const* d_in, const int* in_sizes, int n_in,
                              void* d_out, int out_size) {
    const float* x    = (const float*)d_in[0];   // [B,S,F]
    const float* Wa   = (const float*)d_in[1];   // [H,F]
    // d_in[2] = b_att: unused (softmax over s is shift-invariant per (b,h))
    const float* Wg   = (const float*)d_in[3];   // [H,F]
    const float* bg   = (const float*)d_in[4];   // [H]
    const float* Wout = (const float*)d_in[5];   // [F, H*F]
    const float* bout = (const float*)d_in[6];   // [F]
    float* out = (float*)d_out;                  // [B,F]

    k_init<<<B_, 256>>>(bout, out);
    k_logits<<<ROWS_/32, 256>>>(x, Wa, Wg);
    k_stats<<<B_*H_, 256>>>();
    k_pool<<<dim3(32, B_), 192>>>(x, bg);
    k_out4<<<dim3(F_/NT_, KDIM_/KT_), 256>>>(Wout, out);
}